// round 2
// baseline (speedup 1.0000x reference)
#include <cuda_runtime.h>
#include <cuda_bf16.h>
#include <math.h>

#define NN      16384
#define EE      262144
#define HID     128
#define NGAUSS  50
#define NINTER  6
#define NTAB    4096
#define DMAX    8.6610f
#define DELTA   (DMAX / (float)(NTAB - 1))
#define GSPACE  (10.0f / 49.0f)
#define GCOEFF  (-0.5f / (GSPACE * GSPACE))
#define LOG2F_C 0.69314718055994530942f
#define PI_O10  0.31415926535897932f

// ---------------- device scratch (no allocations allowed) ----------------
__device__ float g_d[EE];
__device__ int   g_perm[EE];
__device__ int   g_start[NN + 1];
__device__ int   g_cnt[NN];
__device__ float g_h[NN * HID];
__device__ float g_x[NN * HID];
__device__ float g_agg[NN * HID];
__device__ float g_t1[NN * HID];
__device__ float g_H[NINTER * NTAB * HID];   // filter hidden layer table
__device__ float g_T[NINTER * NTAB * HID];   // final filter tables
__device__ float g_C[NTAB];
__device__ float g_sum;

__device__ __forceinline__ float sspf(float x) {
    float sp = (x > 15.0f) ? x : log1pf(expf(x));
    return sp - LOG2F_C;
}

// ---------------- prep: zero counters ----------------
__global__ void zero_kernel() {
    int i = blockIdx.x * blockDim.x + threadIdx.x;
    if (i < NN) g_cnt[i] = 0;
    if (i == 0) g_sum = 0.0f;
}

// ---------------- edge distances + dst histogram ----------------
__global__ void prep_kernel(const float* __restrict__ pos, const int* __restrict__ ei) {
    int e = blockIdx.x * blockDim.x + threadIdx.x;
    if (e >= EE) return;
    int s = ei[e];
    int t = ei[EE + e];
    float dx = pos[3 * s + 0] - pos[3 * t + 0];
    float dy = pos[3 * s + 1] - pos[3 * t + 1];
    float dz = pos[3 * s + 2] - pos[3 * t + 2];
    g_d[e] = sqrtf(dx * dx + dy * dy + dz * dz);
    atomicAdd(&g_cnt[t], 1);
}

// ---------------- exclusive scan of counts (N=16384, one block) ----------------
__global__ void scan_kernel() {
    __shared__ int part[1024];
    int tid = threadIdx.x;
    int base = tid * 16;
    int loc[16];
    int s = 0;
#pragma unroll
    for (int i = 0; i < 16; i++) { loc[i] = g_cnt[base + i]; s += loc[i]; }
    part[tid] = s;
    __syncthreads();
    for (int off = 1; off < 1024; off <<= 1) {
        int v = part[tid];
        int add = (tid >= off) ? part[tid - off] : 0;
        __syncthreads();
        part[tid] = v + add;
        __syncthreads();
    }
    int excl = (tid == 0) ? 0 : part[tid - 1];
#pragma unroll
    for (int i = 0; i < 16; i++) {
        g_start[base + i] = excl;
        g_cnt[base + i] = excl;   // cursor init
        excl += loc[i];
    }
    if (tid == 1023) g_start[NN] = excl;
}

// ---------------- scatter edge ids into dst-sorted order ----------------
__global__ void scatter_kernel(const int* __restrict__ ei) {
    int e = blockIdx.x * blockDim.x + threadIdx.x;
    if (e >= EE) return;
    int t = ei[EE + e];
    int p = atomicAdd(&g_cnt[t], 1);
    g_perm[p] = e;
}

// ---------------- h init from embedding ----------------
__global__ void emb_kernel(const int* __restrict__ z, const float* __restrict__ emb) {
    int idx = blockIdx.x * blockDim.x + threadIdx.x;
    if (idx >= NN * HID) return;
    int n = idx >> 7, c = idx & 127;
    g_h[idx] = emb[z[n] * HID + c];
}

// ---------------- cosine-cutoff vector over table abscissae ----------------
__global__ void cvec_kernel() {
    int t = blockIdx.x * blockDim.x + threadIdx.x;
    if (t >= NTAB) return;
    float dt = t * DELTA;
    g_C[t] = 0.5f * (cosf(dt * PI_O10) + 1.0f);
}

// ---------------- filter hidden table: H_i[t] = ssp(ea(t)@Wf1_i + bf1_i) ----------------
__global__ void tableH_kernel(const float* __restrict__ Wf1, const float* __restrict__ bf1) {
    int inter = blockIdx.y;
    int tbase = blockIdx.x * 8;
    __shared__ float W1s[NGAUSS * HID];
    __shared__ float eas[8][NGAUSS];
    const float* W1 = Wf1 + inter * NGAUSS * HID;
    for (int i = threadIdx.x; i < NGAUSS * HID; i += 128) W1s[i] = W1[i];
    for (int i = threadIdx.x; i < 8 * NGAUSS; i += 128) {
        int r = i / NGAUSS, k = i % NGAUSS;
        float dt = (tbase + r) * DELTA;
        float u = dt - k * GSPACE;
        eas[r][k] = expf(GCOEFF * u * u);
    }
    __syncthreads();
    float b = bf1[inter * HID + threadIdx.x];
#pragma unroll
    for (int r = 0; r < 8; r++) {
        float s = b;
#pragma unroll
        for (int k = 0; k < NGAUSS; k++) s += eas[r][k] * W1s[k * HID + threadIdx.x];
        g_H[(inter * NTAB + tbase + r) * HID + threadIdx.x] = sspf(s);
    }
}

// ---------------- unified fp32 GEMM: M x 128 x 128, A,B,C row-major ----------------
#define MODE_PLAIN 0
#define MODE_SSP   1
#define MODE_RES   2
#define MODE_FILT  3

template <int MODE>
__global__ void gemm128_kernel(const float* __restrict__ A, const float* __restrict__ B,
                               const float* __restrict__ bias, const float* __restrict__ extra,
                               float* __restrict__ Cout) {
    const int tid = threadIdx.x;           // 256 threads
    const int row0 = blockIdx.x * 64;
    __shared__ float As[64][33];
    __shared__ float4 Bs[32][32];
    const int lane = tid & 31;             // columns lane*4 .. lane*4+3
    const int rgrp = tid >> 5;             // rows rgrp*8 .. +7
    float acc[8][4] = {};

    for (int kt = 0; kt < 128; kt += 32) {
#pragma unroll
        for (int it = 0; it < 8; it++) {
            int idx = tid + it * 256;
            int r = idx >> 5, c = idx & 31;
            As[r][c] = A[(row0 + r) * 128 + kt + c];
        }
#pragma unroll
        for (int it = 0; it < 4; it++) {
            int idx = tid + it * 256;
            int r = idx >> 5, c4 = idx & 31;
            Bs[r][c4] = ((const float4*)B)[(kt + r) * 32 + c4];
        }
        __syncthreads();
#pragma unroll
        for (int k = 0; k < 32; k++) {
            float4 b = Bs[k][lane];
#pragma unroll
            for (int r = 0; r < 8; r++) {
                float a = As[(rgrp << 3) + r][k];
                acc[r][0] += a * b.x;
                acc[r][1] += a * b.y;
                acc[r][2] += a * b.z;
                acc[r][3] += a * b.w;
            }
        }
        __syncthreads();
    }

    int c0 = lane * 4;
    float4 bv = make_float4(0.f, 0.f, 0.f, 0.f);
    if (MODE != MODE_PLAIN) bv = *(const float4*)(bias + c0);
#pragma unroll
    for (int r = 0; r < 8; r++) {
        int row = row0 + (rgrp << 3) + r;
        float vx = acc[r][0] + bv.x;
        float vy = acc[r][1] + bv.y;
        float vz = acc[r][2] + bv.z;
        float vw = acc[r][3] + bv.w;
        if (MODE == MODE_SSP) {
            vx = sspf(vx); vy = sspf(vy); vz = sspf(vz); vw = sspf(vw);
        }
        if (MODE == MODE_RES) {
            float4 rv = *(const float4*)(extra + row * 128 + c0);
            vx += rv.x; vy += rv.y; vz += rv.z; vw += rv.w;
        }
        if (MODE == MODE_FILT) {
            float cs = extra[row];
            vx *= cs; vy *= cs; vz *= cs; vw *= cs;
        }
        *(float4*)(Cout + row * 128 + c0) = make_float4(vx, vy, vz, vw);
    }
}

// ---------------- edge aggregation: warp per node, dst-sorted, no atomics ----------------
__global__ void agg_kernel(const float* __restrict__ x, const float* __restrict__ T,
                           const int* __restrict__ ei) {
    int warp = (blockIdx.x * blockDim.x + threadIdx.x) >> 5;
    int lane = threadIdx.x & 31;
    if (warp >= NN) return;
    int b = g_start[warp];
    int e = g_start[warp + 1];
    float4 acc = make_float4(0.f, 0.f, 0.f, 0.f);
    const float invd = 1.0f / DELTA;
    for (int j = b; j < e; j++) {
        int eid = g_perm[j];
        int s = ei[eid];                 // src
        float dd = g_d[eid];
        float f = dd * invd;
        int t0 = (int)f;
        t0 = min(t0, NTAB - 2);
        float w = f - (float)t0;
        float w0 = 1.0f - w;
        const float4* xr = (const float4*)(x + s * 128);
        const float4* T0 = (const float4*)(T + t0 * 128);
        const float4* T1 = T0 + 32;
        float4 xv = xr[lane];
        float4 a0 = T0[lane];
        float4 a1 = T1[lane];
        acc.x += xv.x * (w0 * a0.x + w * a1.x);
        acc.y += xv.y * (w0 * a0.y + w * a1.y);
        acc.z += xv.z * (w0 * a0.z + w * a1.z);
        acc.w += xv.w * (w0 * a0.w + w * a1.w);
    }
    ((float4*)(g_agg + warp * 128))[lane] = acc;
}

// ---------------- output head: per-node MLP + global sum ----------------
__global__ void out_kernel(const float* __restrict__ Wo1, const float* __restrict__ bo1,
                           const float* __restrict__ Wo2) {
    int node = blockIdx.x * 4 + (threadIdx.x >> 6);
    int t = threadIdx.x & 63;
    const float* hr = g_h + node * 128;
    float s = bo1[t];
#pragma unroll
    for (int k = 0; k < 128; k++) s += hr[k] * Wo1[k * 64 + t];
    float v = sspf(s) * Wo2[t];
#pragma unroll
    for (int off = 16; off > 0; off >>= 1)
        v += __shfl_xor_sync(0xFFFFFFFFu, v, off);
    if ((threadIdx.x & 31) == 0) atomicAdd(&g_sum, v);
}

__global__ void final_kernel(float* __restrict__ out, const float* __restrict__ bo2) {
    float v = g_sum + (float)NN * bo2[0];
    out[0] = fmaxf(v, 0.0f);
}

// ---------------- launch ----------------
extern "C" void kernel_launch(void* const* d_in, const int* in_sizes, int n_in,
                              void* d_out, int out_size) {
    const int*   z    = (const int*)d_in[0];
    const float* pos  = (const float*)d_in[1];
    const int*   ei   = (const int*)d_in[2];
    const float* emb  = (const float*)d_in[3];
    const float* Wf1  = (const float*)d_in[4];
    const float* bf1  = (const float*)d_in[5];
    const float* Wf2  = (const float*)d_in[6];
    const float* bf2  = (const float*)d_in[7];
    const float* Wl1  = (const float*)d_in[8];
    const float* Wl2  = (const float*)d_in[9];
    const float* bl2  = (const float*)d_in[10];
    const float* Wl   = (const float*)d_in[11];
    const float* bl   = (const float*)d_in[12];
    const float* Wo1  = (const float*)d_in[13];
    const float* bo1  = (const float*)d_in[14];
    const float* Wo2  = (const float*)d_in[15];
    const float* bo2  = (const float*)d_in[16];
    float* out = (float*)d_out;

    float *p_h, *p_x, *p_agg, *p_t1, *p_H, *p_T, *p_C;
    cudaGetSymbolAddress((void**)&p_h,   g_h);
    cudaGetSymbolAddress((void**)&p_x,   g_x);
    cudaGetSymbolAddress((void**)&p_agg, g_agg);
    cudaGetSymbolAddress((void**)&p_t1,  g_t1);
    cudaGetSymbolAddress((void**)&p_H,   g_H);
    cudaGetSymbolAddress((void**)&p_T,   g_T);
    cudaGetSymbolAddress((void**)&p_C,   g_C);

    // --- edge prep + dst sort ---
    zero_kernel<<<NN / 256, 256>>>();
    prep_kernel<<<EE / 256, 256>>>(pos, ei);
    scan_kernel<<<1, 1024>>>();
    scatter_kernel<<<EE / 256, 256>>>(ei);
    emb_kernel<<<NN * HID / 256, 256>>>(z, emb);

    // --- filter tables (function of scalar distance only) ---
    cvec_kernel<<<NTAB / 256, 256>>>();
    tableH_kernel<<<dim3(NTAB / 8, NINTER), 128>>>(Wf1, bf1);
    for (int i = 0; i < NINTER; i++) {
        gemm128_kernel<MODE_FILT><<<NTAB / 64, 256>>>(
            p_H + i * NTAB * HID, Wf2 + i * HID * HID,
            bf2 + i * HID, p_C, p_T + i * NTAB * HID);
    }

    // --- interaction blocks ---
    for (int i = 0; i < NINTER; i++) {
        gemm128_kernel<MODE_PLAIN><<<NN / 64, 256>>>(
            p_h, Wl1 + i * HID * HID, nullptr, nullptr, p_x);
        agg_kernel<<<NN / 8, 256>>>(p_x, p_T + i * NTAB * HID, ei);
        gemm128_kernel<MODE_SSP><<<NN / 64, 256>>>(
            p_agg, Wl2 + i * HID * HID, bl2 + i * HID, nullptr, p_t1);
        gemm128_kernel<MODE_RES><<<NN / 64, 256>>>(
            p_t1, Wl + i * HID * HID, bl + i * HID, p_h, p_h);
    }

    // --- readout ---
    out_kernel<<<NN / 4, 256>>>(Wo1, bo1, Wo2);
    final_kernel<<<1, 1>>>(out, bo2);
}

// round 5
// speedup vs baseline: 1.2443x; 1.2443x over previous
#include <cuda_runtime.h>
#include <cuda_bf16.h>
#include <math.h>
#include <cstdint>

#define NN      16384
#define EE      262144
#define HID     128
#define NGAUSS  50
#define NINTER  6
#define NTAB    4096
#define DMAX    8.6610f
#define DELTA   (DMAX / (float)(NTAB - 1))
#define GSPACE  (10.0f / 49.0f)
#define GCOEFF  (-0.5f / (GSPACE * GSPACE))
#define LOG2F_C 0.69314718055994530942f
#define PI_O10  0.31415926535897932f

// ---------------- device scratch ----------------
__device__ float g_d[EE];
__device__ int   g_perm[EE];     // packed (t0 << 16) | src
__device__ float g_pw[EE];       // lerp weight
__device__ int   g_start[NN + 1];
__device__ int   g_cnt[NN];
__device__ float g_h[NN * HID];
__device__ __nv_bfloat16 g_xb[NN * HID];
__device__ float g_agg[NN * HID];
__device__ float g_t1[NN * HID];
__device__ float g_H[NINTER * NTAB * HID];
__device__ __nv_bfloat16 g_Tb[NINTER * NTAB * HID];
__device__ float g_C[NTAB];
__device__ float g_sum;

__device__ __forceinline__ float sspf(float x) {
    float sp = (x > 15.0f) ? x : log1pf(expf(x));
    return sp - LOG2F_C;
}

// ---------------- prep kernels ----------------
__global__ void zero_kernel() {
    int i = blockIdx.x * blockDim.x + threadIdx.x;
    if (i < NN) g_cnt[i] = 0;
    if (i == 0) g_sum = 0.0f;
}

__global__ void prep_kernel(const float* __restrict__ pos, const int* __restrict__ ei) {
    int e = blockIdx.x * blockDim.x + threadIdx.x;
    if (e >= EE) return;
    int s = ei[e];
    int t = ei[EE + e];
    float dx = pos[3 * s + 0] - pos[3 * t + 0];
    float dy = pos[3 * s + 1] - pos[3 * t + 1];
    float dz = pos[3 * s + 2] - pos[3 * t + 2];
    g_d[e] = sqrtf(dx * dx + dy * dy + dz * dz);
    atomicAdd(&g_cnt[t], 1);
}

__global__ void scan_kernel() {
    __shared__ int part[1024];
    int tid = threadIdx.x;
    int base = tid * 16;
    int loc[16];
    int s = 0;
#pragma unroll
    for (int i = 0; i < 16; i++) { loc[i] = g_cnt[base + i]; s += loc[i]; }
    part[tid] = s;
    __syncthreads();
    for (int off = 1; off < 1024; off <<= 1) {
        int v = part[tid];
        int add = (tid >= off) ? part[tid - off] : 0;
        __syncthreads();
        part[tid] = v + add;
        __syncthreads();
    }
    int excl = (tid == 0) ? 0 : part[tid - 1];
#pragma unroll
    for (int i = 0; i < 16; i++) {
        g_start[base + i] = excl;
        g_cnt[base + i] = excl;
        excl += loc[i];
    }
    if (tid == 1023) g_start[NN] = excl;
}

__global__ void scatter_kernel(const int* __restrict__ ei) {
    int e = blockIdx.x * blockDim.x + threadIdx.x;
    if (e >= EE) return;
    int t = ei[EE + e];
    int s = ei[e];
    float dd = g_d[e];
    float f = dd * (1.0f / DELTA);
    int t0 = (int)f;
    t0 = min(t0, NTAB - 2);
    float w = f - (float)t0;
    int p = atomicAdd(&g_cnt[t], 1);
    g_perm[p] = (t0 << 16) | s;
    g_pw[p] = w;
}

__global__ void emb_kernel(const int* __restrict__ z, const float* __restrict__ emb) {
    int idx = blockIdx.x * blockDim.x + threadIdx.x;
    if (idx >= NN * HID) return;
    int n = idx >> 7, c = idx & 127;
    g_h[idx] = emb[z[n] * HID + c];
}

__global__ void cvec_kernel() {
    int t = blockIdx.x * blockDim.x + threadIdx.x;
    if (t >= NTAB) return;
    float dt = t * DELTA;
    g_C[t] = 0.5f * (cosf(dt * PI_O10) + 1.0f);
}

__global__ void tableH_kernel(const float* __restrict__ Wf1, const float* __restrict__ bf1) {
    int inter = blockIdx.y;
    int tbase = blockIdx.x * 8;
    __shared__ float W1s[NGAUSS * HID];
    __shared__ float eas[8][NGAUSS];
    const float* W1 = Wf1 + inter * NGAUSS * HID;
    for (int i = threadIdx.x; i < NGAUSS * HID; i += 128) W1s[i] = W1[i];
    for (int i = threadIdx.x; i < 8 * NGAUSS; i += 128) {
        int r = i / NGAUSS, k = i % NGAUSS;
        float dt = (tbase + r) * DELTA;
        float u = dt - k * GSPACE;
        eas[r][k] = expf(GCOEFF * u * u);
    }
    __syncthreads();
    float b = bf1[inter * HID + threadIdx.x];
#pragma unroll
    for (int r = 0; r < 8; r++) {
        float s = b;
#pragma unroll
        for (int k = 0; k < NGAUSS; k++) s += eas[r][k] * W1s[k * HID + threadIdx.x];
        g_H[(inter * NTAB + tbase + r) * HID + threadIdx.x] = sspf(s);
    }
}

// ---------------- tensor-core GEMM (mma.sync bf16 split, fp32 accum) ----------------
#define MODE_PLAIN 0
#define MODE_SSP   1
#define MODE_RES   2
#define MODE_FILT  3

#define MMA16816(d, a, b0, b1) \
    asm volatile("mma.sync.aligned.m16n8k16.row.col.f32.bf16.bf16.f32 " \
        "{%0,%1,%2,%3}, {%4,%5,%6,%7}, {%8,%9}, {%0,%1,%2,%3};" \
        : "+f"((d)[0]), "+f"((d)[1]), "+f"((d)[2]), "+f"((d)[3]) \
        : "r"((a)[0]), "r"((a)[1]), "r"((a)[2]), "r"((a)[3]), "r"(b0), "r"(b1))

__device__ __forceinline__ void split2(float2 f, uint32_t& hi, uint32_t& lo) {
    __nv_bfloat162 h = __floats2bfloat162_rn(f.x, f.y);
    float lx = f.x - __bfloat162float(h.x);
    float ly = f.y - __bfloat162float(h.y);
    __nv_bfloat162 l = __floats2bfloat162_rn(lx, ly);
    hi = *(uint32_t*)&h;
    lo = *(uint32_t*)&l;
}

// C[M x 128] = A[M x 128] @ W[128 x 128]; per-y-block strides allow batching.
template <int MODE>
__global__ __launch_bounds__(256) void gemm_mma(
    const float* __restrict__ A, const float* __restrict__ W,
    const float* __restrict__ bias, const float* __restrict__ extra,
    float* __restrict__ outF, __nv_bfloat16* __restrict__ outB,
    size_t aStride, size_t wStride, size_t bStride, size_t oStride)
{
    __shared__ __nv_bfloat16 sBhi[128][72];
    __shared__ __nv_bfloat16 sBlo[128][72];

    A += (size_t)blockIdx.y * aStride;
    W += (size_t)blockIdx.y * wStride;
    if (bias) bias += (size_t)blockIdx.y * bStride;
    if (outF) outF += (size_t)blockIdx.y * oStride;
    if (outB) outB += (size_t)blockIdx.y * oStride;
    if (MODE == MODE_RES) extra += (size_t)blockIdx.y * oStride;

    const int tid = threadIdx.x;
    const int w = tid >> 5, lane = tid & 31;
    const int wm = w >> 1, wn = w & 1;
    const int g = lane >> 2, tg = lane & 3;
    const int row0 = blockIdx.x * 128;

    float acc[2][8][4] = {};
    const float* aBase = A + (size_t)(row0 + wm * 32 + g) * 128;

    for (int kh = 0; kh < 2; kh++) {
        __syncthreads();
        for (int idx = tid; idx < 64 * 128; idx += 256) {
            int kp = idx >> 7, n = idx & 127;
            float v = W[(size_t)(kh * 64 + kp) * 128 + n];
            __nv_bfloat16 h = __float2bfloat16(v);
            __nv_bfloat16 l = __float2bfloat16(v - __bfloat162float(h));
            sBhi[n][kp] = h;
            sBlo[n][kp] = l;
        }
        __syncthreads();

#pragma unroll
        for (int ks = 0; ks < 4; ks++) {
            int kc = kh * 64 + ks * 16 + tg * 2;
            uint32_t ahi[2][4], alo[2][4];
#pragma unroll
            for (int mt = 0; mt < 2; mt++) {
                const float* rp = aBase + (size_t)mt * 16 * 128;
                float2 f0 = *(const float2*)(rp + kc);
                float2 f1 = *(const float2*)(rp + 8 * 128 + kc);
                float2 f2 = *(const float2*)(rp + kc + 8);
                float2 f3 = *(const float2*)(rp + 8 * 128 + kc + 8);
                split2(f0, ahi[mt][0], alo[mt][0]);
                split2(f1, ahi[mt][1], alo[mt][1]);
                split2(f2, ahi[mt][2], alo[mt][2]);
                split2(f3, ahi[mt][3], alo[mt][3]);
            }
            int c = ks * 16 + tg * 2;
#pragma unroll
            for (int nt = 0; nt < 8; nt++) {
                int n = wn * 64 + nt * 8 + g;
                uint32_t bhi0 = *(const uint32_t*)&sBhi[n][c];
                uint32_t bhi1 = *(const uint32_t*)&sBhi[n][c + 8];
                uint32_t blo0 = *(const uint32_t*)&sBlo[n][c];
                uint32_t blo1 = *(const uint32_t*)&sBlo[n][c + 8];
#pragma unroll
                for (int mt = 0; mt < 2; mt++) {
                    MMA16816(acc[mt][nt], ahi[mt], bhi0, bhi1);
                    MMA16816(acc[mt][nt], ahi[mt], blo0, blo1);
                    MMA16816(acc[mt][nt], alo[mt], bhi0, bhi1);
                }
            }
        }
    }

    // ---- epilogue ----
#pragma unroll
    for (int mt = 0; mt < 2; mt++) {
        int r0 = row0 + wm * 32 + mt * 16 + g;
        int r1 = r0 + 8;
        float s0 = 1.0f, s1 = 1.0f;
        if (MODE == MODE_FILT) { s0 = extra[r0]; s1 = extra[r1]; }
#pragma unroll
        for (int nt = 0; nt < 8; nt++) {
            int cc = wn * 64 + nt * 8 + tg * 2;
            float vx0 = acc[mt][nt][0], vy0 = acc[mt][nt][1];
            float vx1 = acc[mt][nt][2], vy1 = acc[mt][nt][3];
            if (MODE != MODE_PLAIN) {
                float2 bv = *(const float2*)(bias + cc);
                vx0 += bv.x; vy0 += bv.y; vx1 += bv.x; vy1 += bv.y;
            }
            if (MODE == MODE_SSP) {
                vx0 = sspf(vx0); vy0 = sspf(vy0); vx1 = sspf(vx1); vy1 = sspf(vy1);
            }
            if (MODE == MODE_RES) {
                float2 e0 = *(const float2*)(extra + (size_t)r0 * 128 + cc);
                float2 e1 = *(const float2*)(extra + (size_t)r1 * 128 + cc);
                vx0 += e0.x; vy0 += e0.y; vx1 += e1.x; vy1 += e1.y;
            }
            if (MODE == MODE_FILT) {
                vx0 *= s0; vy0 *= s0; vx1 *= s1; vy1 *= s1;
            }
            if (MODE == MODE_PLAIN || MODE == MODE_FILT) {
                __nv_bfloat162 o0 = __floats2bfloat162_rn(vx0, vy0);
                __nv_bfloat162 o1 = __floats2bfloat162_rn(vx1, vy1);
                *(__nv_bfloat162*)(outB + (size_t)r0 * 128 + cc) = o0;
                *(__nv_bfloat162*)(outB + (size_t)r1 * 128 + cc) = o1;
            } else {
                *(float2*)(outF + (size_t)r0 * 128 + cc) = make_float2(vx0, vy0);
                *(float2*)(outF + (size_t)r1 * 128 + cc) = make_float2(vx1, vy1);
            }
        }
    }
}

// ---------------- edge aggregation (dst-sorted, warp per node, bf16 inputs) ----------------
__global__ void agg_kernel(const __nv_bfloat16* __restrict__ xb,
                           const __nv_bfloat16* __restrict__ Tb) {
    int warp = (blockIdx.x * blockDim.x + threadIdx.x) >> 5;
    int lane = threadIdx.x & 31;
    if (warp >= NN) return;
    int b = g_start[warp];
    int e = g_start[warp + 1];
    float4 acc = make_float4(0.f, 0.f, 0.f, 0.f);
    for (int j = b; j < e; j++) {
        int pk = g_perm[j];
        float wt = g_pw[j];
        int s = pk & 0xFFFF;
        int t0 = pk >> 16;
        uint2 xv = ((const uint2*)(xb + (size_t)s * 128))[lane];
        uint2 a0 = ((const uint2*)(Tb + (size_t)t0 * 128))[lane];
        uint2 a1 = ((const uint2*)(Tb + (size_t)(t0 + 1) * 128))[lane];
        float2 x0 = __bfloat1622float2(*(__nv_bfloat162*)&xv.x);
        float2 x1 = __bfloat1622float2(*(__nv_bfloat162*)&xv.y);
        float2 p0 = __bfloat1622float2(*(__nv_bfloat162*)&a0.x);
        float2 p1 = __bfloat1622float2(*(__nv_bfloat162*)&a0.y);
        float2 q0 = __bfloat1622float2(*(__nv_bfloat162*)&a1.x);
        float2 q1 = __bfloat1622float2(*(__nv_bfloat162*)&a1.y);
        float w0 = 1.0f - wt;
        acc.x += x0.x * (w0 * p0.x + wt * q0.x);
        acc.y += x0.y * (w0 * p0.y + wt * q0.y);
        acc.z += x1.x * (w0 * p1.x + wt * q1.x);
        acc.w += x1.y * (w0 * p1.y + wt * q1.y);
    }
    ((float4*)(g_agg + (size_t)warp * 128))[lane] = acc;
}

// ---------------- output head ----------------
__global__ void out_kernel(const float* __restrict__ Wo1, const float* __restrict__ bo1,
                           const float* __restrict__ Wo2) {
    int node = blockIdx.x * 4 + (threadIdx.x >> 6);
    int t = threadIdx.x & 63;
    const float* hr = g_h + (size_t)node * 128;
    float s = bo1[t];
#pragma unroll
    for (int k = 0; k < 128; k++) s += hr[k] * Wo1[k * 64 + t];
    float v = sspf(s) * Wo2[t];
#pragma unroll
    for (int off = 16; off > 0; off >>= 1)
        v += __shfl_xor_sync(0xFFFFFFFFu, v, off);
    if ((threadIdx.x & 31) == 0) atomicAdd(&g_sum, v);
}

__global__ void final_kernel(float* __restrict__ out, const float* __restrict__ bo2) {
    float v = g_sum + (float)NN * bo2[0];
    out[0] = fmaxf(v, 0.0f);
}

// ---------------- launch ----------------
extern "C" void kernel_launch(void* const* d_in, const int* in_sizes, int n_in,
                              void* d_out, int out_size) {
    const int*   z    = (const int*)d_in[0];
    const float* pos  = (const float*)d_in[1];
    const int*   ei   = (const int*)d_in[2];
    const float* emb  = (const float*)d_in[3];
    const float* Wf1  = (const float*)d_in[4];
    const float* bf1  = (const float*)d_in[5];
    const float* Wf2  = (const float*)d_in[6];
    const float* bf2  = (const float*)d_in[7];
    const float* Wl1  = (const float*)d_in[8];
    const float* Wl2  = (const float*)d_in[9];
    const float* bl2  = (const float*)d_in[10];
    const float* Wl   = (const float*)d_in[11];
    const float* bl   = (const float*)d_in[12];
    const float* Wo1  = (const float*)d_in[13];
    const float* bo1  = (const float*)d_in[14];
    const float* Wo2  = (const float*)d_in[15];
    const float* bo2  = (const float*)d_in[16];
    float* out = (float*)d_out;

    float *p_h, *p_agg, *p_t1, *p_H, *p_C;
    __nv_bfloat16 *p_xb, *p_Tb;
    cudaGetSymbolAddress((void**)&p_h,   g_h);
    cudaGetSymbolAddress((void**)&p_agg, g_agg);
    cudaGetSymbolAddress((void**)&p_t1,  g_t1);
    cudaGetSymbolAddress((void**)&p_H,   g_H);
    cudaGetSymbolAddress((void**)&p_C,   g_C);
    cudaGetSymbolAddress((void**)&p_xb,  g_xb);
    cudaGetSymbolAddress((void**)&p_Tb,  g_Tb);

    // --- edge prep + dst sort ---
    zero_kernel<<<NN / 256, 256>>>();
    prep_kernel<<<EE / 256, 256>>>(pos, ei);
    scan_kernel<<<1, 1024>>>();
    scatter_kernel<<<EE / 256, 256>>>(ei);
    emb_kernel<<<NN * HID / 256, 256>>>(z, emb);

    // --- filter tables (batched over all 6 interactions) ---
    cvec_kernel<<<NTAB / 256, 256>>>();
    tableH_kernel<<<dim3(NTAB / 8, NINTER), 128>>>(Wf1, bf1);
    gemm_mma<MODE_FILT><<<dim3(NTAB / 128, NINTER), 256>>>(
        p_H, Wf2, bf2, p_C, nullptr, p_Tb,
        (size_t)NTAB * HID, (size_t)HID * HID, (size_t)HID, (size_t)NTAB * HID);

    // --- interaction blocks ---
    for (int i = 0; i < NINTER; i++) {
        gemm_mma<MODE_PLAIN><<<NN / 128, 256>>>(
            p_h, Wl1 + (size_t)i * HID * HID, nullptr, nullptr, nullptr, p_xb, 0, 0, 0, 0);
        agg_kernel<<<NN / 8, 256>>>(p_xb, p_Tb + (size_t)i * NTAB * HID);
        gemm_mma<MODE_SSP><<<NN / 128, 256>>>(
            p_agg, Wl2 + (size_t)i * HID * HID, bl2 + (size_t)i * HID, nullptr,
            p_t1, nullptr, 0, 0, 0, 0);
        gemm_mma<MODE_RES><<<NN / 128, 256>>>(
            p_t1, Wl + (size_t)i * HID * HID, bl + (size_t)i * HID, p_h,
            p_h, nullptr, 0, 0, 0, 0);
    }

    // --- readout ---
    out_kernel<<<NN / 4, 256>>>(Wo1, bo1, Wo2);
    final_kernel<<<1, 1>>>(out, bo2);
}